// round 1
// baseline (speedup 1.0000x reference)
#include <cuda_runtime.h>
#include <math.h>

// Shapes (fixed by the problem)
#define HD      1024
#define NROWS   50000
#define GRID_B  304          // 2 CTAs per SM on 152 SMs
#define WARPS_B 8
#define TOT_WARPS (GRID_B * WARPS_B)
#define NP4     (HD / 4)     // 256 float4 positions per 1024-float vector

// Scratch (__device__ globals: no allocation allowed in kernel_launch)
__device__ float  g_q[HD];                       // query vector
__device__ float4 g_epartT[NP4 * GRID_B];        // [position][cta] transposed partials
__device__ float  g_Zpart[GRID_B];               // per-CTA partition-function partials
__device__ float  g_es[HD];                      // unnormalized weighted sum

// ---------------------------------------------------------------------------
// Kernel A: q[j] = dot(W0[j,:], h_t) + b0[j]      grid 128 x 256 (warp per row)
// ---------------------------------------------------------------------------
__global__ __launch_bounds__(256) void kA(const float* __restrict__ W0,
                                          const float* __restrict__ ht,
                                          const float* __restrict__ b0) {
    __shared__ float4 sht[NP4];
    int tid = threadIdx.x;
    sht[tid] = ((const float4*)ht)[tid];
    __syncthreads();

    int wid = tid >> 5, lane = tid & 31;
    int j = blockIdx.x * 8 + wid;                 // 0..1023
    const float4* wr = (const float4*)(W0 + (size_t)j * HD);

    float s = 0.f;
#pragma unroll
    for (int k = 0; k < 8; k++) {
        float4 w4 = wr[lane + 32 * k];
        float4 h4 = sht[lane + 32 * k];
        s = fmaf(w4.x, h4.x, s); s = fmaf(w4.y, h4.y, s);
        s = fmaf(w4.z, h4.z, s); s = fmaf(w4.w, h4.w, s);
    }
#pragma unroll
    for (int o = 16; o; o >>= 1) s += __shfl_xor_sync(0xffffffffu, s, o);
    if (lane == 0) g_q[j] = s + b0[j];
}

// ---------------------------------------------------------------------------
// Kernel B: single fused pass over H.
//   Per row i: s = H_i . q ; u = exp(exp(s)) ; Z += u ; e += u * H_i
//   Row stays in registers for both the dot and the accumulate -> H read ONCE.
// ---------------------------------------------------------------------------
__global__ __launch_bounds__(256, 2) void kB(const float* __restrict__ H) {
    __shared__ float4 sq[NP4];                    // query, 4 KB
    __shared__ float4 se[WARPS_B][NP4];           // per-warp partials, 32 KB
    __shared__ float  sZ[WARPS_B];

    int tid = threadIdx.x;
    sq[tid] = ((const float4*)g_q)[tid];
    __syncthreads();

    int wid = tid >> 5, lane = tid & 31;

    float4 e[8];
#pragma unroll
    for (int k = 0; k < 8; k++) e[k] = make_float4(0.f, 0.f, 0.f, 0.f);
    float Z = 0.f;

    int gw = blockIdx.x * WARPS_B + wid;
    for (int row = gw; row < NROWS; row += TOT_WARPS) {
        const float4* hr = (const float4*)(H + (size_t)row * HD);
        float4 r[8];
#pragma unroll
        for (int k = 0; k < 8; k++) r[k] = hr[lane + 32 * k];   // coalesced 512B bursts

        float s = 0.f;
#pragma unroll
        for (int k = 0; k < 8; k++) {
            float4 q4 = sq[lane + 32 * k];
            s = fmaf(r[k].x, q4.x, s); s = fmaf(r[k].y, q4.y, s);
            s = fmaf(r[k].z, q4.z, s); s = fmaf(r[k].w, q4.w, s);
        }
#pragma unroll
        for (int o = 16; o; o >>= 1) s += __shfl_xor_sync(0xffffffffu, s, o);

        // double exp: scores = exp(H@q); softmax numerator exp(scores).
        // No max-subtraction needed: softmax(t) == exp(t)/sum(exp(t)) exactly,
        // and t is bounded (inputs pre-scaled so this stays finite in fp32).
        float u = expf(expf(s));
        Z += u;
#pragma unroll
        for (int k = 0; k < 8; k++) {
            e[k].x = fmaf(u, r[k].x, e[k].x);
            e[k].y = fmaf(u, r[k].y, e[k].y);
            e[k].z = fmaf(u, r[k].z, e[k].z);
            e[k].w = fmaf(u, r[k].w, e[k].w);
        }
    }

    // CTA-level deterministic reduce of the 8 warp partials
#pragma unroll
    for (int k = 0; k < 8; k++) se[wid][lane + 32 * k] = e[k];
    if (lane == 0) sZ[wid] = Z;
    __syncthreads();

    float4 acc = se[0][tid];
#pragma unroll
    for (int w = 1; w < WARPS_B; w++) {
        float4 v = se[w][tid];
        acc.x += v.x; acc.y += v.y; acc.z += v.z; acc.w += v.w;
    }
    // transposed store: position-major so kernel C reads coalesced
    g_epartT[tid * GRID_B + blockIdx.x] = acc;

    if (tid == 0) {
        float z = 0.f;
#pragma unroll
        for (int w = 0; w < WARPS_B; w++) z += sZ[w];
        g_Zpart[blockIdx.x] = z;
    }
}

// ---------------------------------------------------------------------------
// Kernel C: deterministic reduce of GRID_B partials -> g_es (unnormalized)
//   grid 32 x 256: one warp per float4 position; coalesced contiguous reads.
// ---------------------------------------------------------------------------
__global__ __launch_bounds__(256) void kC() {
    int wid = threadIdx.x >> 5, lane = threadIdx.x & 31;
    int p = blockIdx.x * 8 + wid;                 // 0..255

    float4 acc = make_float4(0.f, 0.f, 0.f, 0.f);
    for (int b = lane; b < GRID_B; b += 32) {
        float4 v = g_epartT[p * GRID_B + b];
        acc.x += v.x; acc.y += v.y; acc.z += v.z; acc.w += v.w;
    }
#pragma unroll
    for (int o = 16; o; o >>= 1) {
        acc.x += __shfl_xor_sync(0xffffffffu, acc.x, o);
        acc.y += __shfl_xor_sync(0xffffffffu, acc.y, o);
        acc.z += __shfl_xor_sync(0xffffffffu, acc.z, o);
        acc.w += __shfl_xor_sync(0xffffffffu, acc.w, o);
    }
    if (lane == 0) ((float4*)g_es)[p] = acc;
}

// ---------------------------------------------------------------------------
// Kernel D: out[j] = tanh( dot(W1[j],e_s)/Z + b1[j] + dot(W2[j],h_t) + b2[j] )
//   (division by Z folded through the linear map)   grid 128 x 256
// ---------------------------------------------------------------------------
__global__ __launch_bounds__(256) void kD(const float* __restrict__ W1,
                                          const float* __restrict__ b1,
                                          const float* __restrict__ W2,
                                          const float* __restrict__ b2,
                                          const float* __restrict__ ht,
                                          float* __restrict__ out) {
    __shared__ float4 ses[NP4];
    __shared__ float4 sht[NP4];
    __shared__ float  sZtot;

    int tid = threadIdx.x;
    ses[tid] = ((const float4*)g_es)[tid];
    sht[tid] = ((const float4*)ht)[tid];
    if (tid < 32) {
        float z = 0.f;
        for (int b = tid; b < GRID_B; b += 32) z += g_Zpart[b];
#pragma unroll
        for (int o = 16; o; o >>= 1) z += __shfl_xor_sync(0xffffffffu, z, o);
        if (tid == 0) sZtot = z;
    }
    __syncthreads();

    int wid = tid >> 5, lane = tid & 31;
    int j = blockIdx.x * 8 + wid;                 // 0..1023
    const float4* w1r = (const float4*)(W1 + (size_t)j * HD);
    const float4* w2r = (const float4*)(W2 + (size_t)j * HD);

    float d1 = 0.f, d2 = 0.f;
#pragma unroll
    for (int k = 0; k < 8; k++) {
        float4 a = w1r[lane + 32 * k];
        float4 v = ses[lane + 32 * k];
        d1 = fmaf(a.x, v.x, d1); d1 = fmaf(a.y, v.y, d1);
        d1 = fmaf(a.z, v.z, d1); d1 = fmaf(a.w, v.w, d1);
        float4 c = w2r[lane + 32 * k];
        float4 h = sht[lane + 32 * k];
        d2 = fmaf(c.x, h.x, d2); d2 = fmaf(c.y, h.y, d2);
        d2 = fmaf(c.z, h.z, d2); d2 = fmaf(c.w, h.w, d2);
    }
#pragma unroll
    for (int o = 16; o; o >>= 1) {
        d1 += __shfl_xor_sync(0xffffffffu, d1, o);
        d2 += __shfl_xor_sync(0xffffffffu, d2, o);
    }
    if (lane == 0)
        out[j] = tanhf(d1 / sZtot + b1[j] + d2 + b2[j]);
}

// ---------------------------------------------------------------------------
extern "C" void kernel_launch(void* const* d_in, const int* in_sizes, int n_in,
                              void* d_out, int out_size) {
    const float* H  = (const float*)d_in[0];
    const float* ht = (const float*)d_in[1];
    const float* W0 = (const float*)d_in[2];
    const float* b0 = (const float*)d_in[3];
    const float* W1 = (const float*)d_in[4];
    const float* b1 = (const float*)d_in[5];
    const float* W2 = (const float*)d_in[6];
    const float* b2 = (const float*)d_in[7];
    float* out = (float*)d_out;

    kA<<<128, 256>>>(W0, ht, b0);
    kB<<<GRID_B, 256>>>(H);
    kC<<<32, 256>>>();
    kD<<<128, 256>>>(W1, b1, W2, b2, ht, out);
}

// round 2
// speedup vs baseline: 1.0150x; 1.0150x over previous
#include <cuda_runtime.h>
#include <math.h>

// Shapes (fixed by the problem)
#define HD      1024
#define NROWS   50000
#define GRID_B  304          // 2 CTAs per SM on 152 SMs
#define WARPS_B 8
#define TOT_WARPS (GRID_B * WARPS_B)
#define NP4     (HD / 4)     // 256 float4 positions per 1024-float vector

// Scratch (__device__ globals: no allocation allowed in kernel_launch)
__device__ float  g_q[HD];                       // query vector
__device__ float4 g_epartT[NP4 * GRID_B];        // [position][cta] transposed partials
__device__ float  g_Zpart[GRID_B];               // per-CTA partition-function partials
__device__ float  g_es[HD];                      // unnormalized weighted sum

// ---------------------------------------------------------------------------
// Kernel A: q[j] = dot(W0[j,:], h_t) + b0[j]      grid 128 x 256 (warp per row)
//   All 8 global LDG.128 issued back-to-back (MLP=8) before any FMA.
// ---------------------------------------------------------------------------
__global__ __launch_bounds__(256) void kA(const float* __restrict__ W0,
                                          const float* __restrict__ ht,
                                          const float* __restrict__ b0) {
    __shared__ float4 sht[NP4];
    int tid = threadIdx.x;
    sht[tid] = ((const float4*)ht)[tid];
    __syncthreads();

    int wid = tid >> 5, lane = tid & 31;
    int j = blockIdx.x * 8 + wid;                 // 0..1023
    const float4* wr = (const float4*)(W0 + (size_t)j * HD);

    float4 w[8];
#pragma unroll
    for (int k = 0; k < 8; k++) w[k] = wr[lane + 32 * k];   // front-batched loads

    float s = 0.f;
#pragma unroll
    for (int k = 0; k < 8; k++) {
        float4 h4 = sht[lane + 32 * k];
        s = fmaf(w[k].x, h4.x, s); s = fmaf(w[k].y, h4.y, s);
        s = fmaf(w[k].z, h4.z, s); s = fmaf(w[k].w, h4.w, s);
    }
#pragma unroll
    for (int o = 16; o; o >>= 1) s += __shfl_xor_sync(0xffffffffu, s, o);
    if (lane == 0) g_q[j] = s + b0[j];
}

// ---------------------------------------------------------------------------
// Kernel B: single fused pass over H.
//   Per row i: s = H_i . q ; u = exp(exp(s)) ; Z += u ; e += u * H_i
//   Row stays in registers for both the dot and the accumulate -> H read ONCE.
// ---------------------------------------------------------------------------
__global__ __launch_bounds__(256, 2) void kB(const float* __restrict__ H) {
    __shared__ float4 sq[NP4];                    // query, 4 KB
    __shared__ float4 se[WARPS_B][NP4];           // per-warp partials, 32 KB
    __shared__ float  sZ[WARPS_B];

    int tid = threadIdx.x;
    sq[tid] = ((const float4*)g_q)[tid];
    __syncthreads();

    int wid = tid >> 5, lane = tid & 31;

    float4 e[8];
#pragma unroll
    for (int k = 0; k < 8; k++) e[k] = make_float4(0.f, 0.f, 0.f, 0.f);
    float Z = 0.f;

    int gw = blockIdx.x * WARPS_B + wid;
    for (int row = gw; row < NROWS; row += TOT_WARPS) {
        const float4* hr = (const float4*)(H + (size_t)row * HD);
        float4 r[8];
#pragma unroll
        for (int k = 0; k < 8; k++) r[k] = hr[lane + 32 * k];   // coalesced 512B bursts

        float s = 0.f;
#pragma unroll
        for (int k = 0; k < 8; k++) {
            float4 q4 = sq[lane + 32 * k];
            s = fmaf(r[k].x, q4.x, s); s = fmaf(r[k].y, q4.y, s);
            s = fmaf(r[k].z, q4.z, s); s = fmaf(r[k].w, q4.w, s);
        }
#pragma unroll
        for (int o = 16; o; o >>= 1) s += __shfl_xor_sync(0xffffffffu, s, o);

        // double exp: scores = exp(H@q); softmax numerator exp(scores).
        // No max-subtraction needed: softmax(t) == exp(t)/sum(exp(t)) exactly,
        // and t is bounded (inputs pre-scaled so this stays finite in fp32).
        float u = expf(expf(s));
        Z += u;
#pragma unroll
        for (int k = 0; k < 8; k++) {
            e[k].x = fmaf(u, r[k].x, e[k].x);
            e[k].y = fmaf(u, r[k].y, e[k].y);
            e[k].z = fmaf(u, r[k].z, e[k].z);
            e[k].w = fmaf(u, r[k].w, e[k].w);
        }
    }

    // CTA-level deterministic reduce of the 8 warp partials
#pragma unroll
    for (int k = 0; k < 8; k++) se[wid][lane + 32 * k] = e[k];
    if (lane == 0) sZ[wid] = Z;
    __syncthreads();

    float4 acc = se[0][tid];
#pragma unroll
    for (int w = 1; w < WARPS_B; w++) {
        float4 v = se[w][tid];
        acc.x += v.x; acc.y += v.y; acc.z += v.z; acc.w += v.w;
    }
    // transposed store: position-major so kernel C reads coalesced
    g_epartT[tid * GRID_B + blockIdx.x] = acc;

    if (tid == 0) {
        float z = 0.f;
#pragma unroll
        for (int w = 0; w < WARPS_B; w++) z += sZ[w];
        g_Zpart[blockIdx.x] = z;
    }
}

// ---------------------------------------------------------------------------
// Kernel C: deterministic reduce of GRID_B partials -> g_es (unnormalized)
//   grid 32 x 256: one warp per float4 position; coalesced contiguous reads.
// ---------------------------------------------------------------------------
__global__ __launch_bounds__(256) void kC() {
    int wid = threadIdx.x >> 5, lane = threadIdx.x & 31;
    int p = blockIdx.x * 8 + wid;                 // 0..255

    float4 acc = make_float4(0.f, 0.f, 0.f, 0.f);
    for (int b = lane; b < GRID_B; b += 32) {
        float4 v = g_epartT[p * GRID_B + b];
        acc.x += v.x; acc.y += v.y; acc.z += v.z; acc.w += v.w;
    }
#pragma unroll
    for (int o = 16; o; o >>= 1) {
        acc.x += __shfl_xor_sync(0xffffffffu, acc.x, o);
        acc.y += __shfl_xor_sync(0xffffffffu, acc.y, o);
        acc.z += __shfl_xor_sync(0xffffffffu, acc.z, o);
        acc.w += __shfl_xor_sync(0xffffffffu, acc.w, o);
    }
    if (lane == 0) ((float4*)g_es)[p] = acc;
}

// ---------------------------------------------------------------------------
// Kernel D: out[j] = tanh( dot(W1[j],e_s)/Z + b1[j] + dot(W2[j],h_t) + b2[j] )
//   (division by Z folded through the linear map)   grid 128 x 256
//   All 16 global LDG.128 (8 of W1, 8 of W2) front-batched -> MLP=16/warp.
// ---------------------------------------------------------------------------
__global__ __launch_bounds__(256) void kD(const float* __restrict__ W1,
                                          const float* __restrict__ b1,
                                          const float* __restrict__ W2,
                                          const float* __restrict__ b2,
                                          const float* __restrict__ ht,
                                          float* __restrict__ out) {
    __shared__ float4 ses[NP4];
    __shared__ float4 sht[NP4];
    __shared__ float  sZtot;

    int tid = threadIdx.x;
    int wid = tid >> 5, lane = tid & 31;
    int j = blockIdx.x * 8 + wid;                 // 0..1023
    const float4* w1r = (const float4*)(W1 + (size_t)j * HD);
    const float4* w2r = (const float4*)(W2 + (size_t)j * HD);

    // Front-batch all 16 global vector loads BEFORE any dependent work.
    float4 a[8], c[8];
#pragma unroll
    for (int k = 0; k < 8; k++) a[k] = w1r[lane + 32 * k];
#pragma unroll
    for (int k = 0; k < 8; k++) c[k] = w2r[lane + 32 * k];

    ses[tid] = ((const float4*)g_es)[tid];
    sht[tid] = ((const float4*)ht)[tid];
    if (tid < 32) {
        float z = 0.f;
        for (int b = tid; b < GRID_B; b += 32) z += g_Zpart[b];
#pragma unroll
        for (int o = 16; o; o >>= 1) z += __shfl_xor_sync(0xffffffffu, z, o);
        if (tid == 0) sZtot = z;
    }
    __syncthreads();

    float d1 = 0.f, d2 = 0.f;
#pragma unroll
    for (int k = 0; k < 8; k++) {
        float4 v = ses[lane + 32 * k];
        d1 = fmaf(a[k].x, v.x, d1); d1 = fmaf(a[k].y, v.y, d1);
        d1 = fmaf(a[k].z, v.z, d1); d1 = fmaf(a[k].w, v.w, d1);
        float4 h = sht[lane + 32 * k];
        d2 = fmaf(c[k].x, h.x, d2); d2 = fmaf(c[k].y, h.y, d2);
        d2 = fmaf(c[k].z, h.z, d2); d2 = fmaf(c[k].w, h.w, d2);
    }
#pragma unroll
    for (int o = 16; o; o >>= 1) {
        d1 += __shfl_xor_sync(0xffffffffu, d1, o);
        d2 += __shfl_xor_sync(0xffffffffu, d2, o);
    }
    if (lane == 0)
        out[j] = tanhf(d1 / sZtot + b1[j] + d2 + b2[j]);
}

// ---------------------------------------------------------------------------
extern "C" void kernel_launch(void* const* d_in, const int* in_sizes, int n_in,
                              void* d_out, int out_size) {
    const float* H  = (const float*)d_in[0];
    const float* ht = (const float*)d_in[1];
    const float* W0 = (const float*)d_in[2];
    const float* b0 = (const float*)d_in[3];
    const float* W1 = (const float*)d_in[4];
    const float* b1 = (const float*)d_in[5];
    const float* W2 = (const float*)d_in[6];
    const float* b2 = (const float*)d_in[7];
    float* out = (float*)d_out;

    kA<<<128, 256>>>(W0, ht, b0);
    kB<<<GRID_B, 256>>>(H);
    kC<<<32, 256>>>();
    kD<<<128, 256>>>(W1, b1, W2, b2, ht, out);
}